// round 12
// baseline (speedup 1.0000x reference)
#include <cuda_runtime.h>
#include <cuda_bf16.h>
#include <cstdint>

// Problem constants (fixed by the dataset instance)
#define NROWS  4096
#define DDIM   1024
#define NCLS   512
#define NNEGS  3679
#define HHALF  7534592u        // n/2 for threefry lane pairing, n = 4096*3679
#define MARGINF 0.15f
#define TTILES 32              // 4096 / 128
#define NTILE  528             // 32*33/2
#define NPERS  296             // persistent grid: exactly 2 CTAs/SM, all wave-1
#define NRNG   148             // rng-role CTAs (one per SM in wave 1)

// loss kernel dynamic smem layout (bytes)
#define STG_BYTES 10240                 // one stage, one matrix: 128*40*2
#define SM_ASM   0                      // 3 stages A: [0, 30720)
#define SM_BSM   30720                  // 3 stages B: [30720, 61440)
#define SM_DP    61440                  // Dp: 256 rows * 9 floats = 9216
#define SM_CTL   70656                  // tile-id broadcast slot
#define SM_TOTAL 70784
// epilogue staging overlays (stage buffers are dead after the mainloop)
#define SM_RF    0                      // fwd bands, 16 KB
#define SM_RR    30720                  // rev bands, 16 KB

// prep kernel grid split
#define PREP_NORM 4096
#define PREP_GRID (PREP_NORM + NCLS)    // 4608

// Scratch (static __device__ arrays: allocation-free)
__device__ __nv_bfloat16 g_xb[NROWS * DDIM];    // normalized samples, bf16
__device__ float g_dpos[NROWS * 8];             // per-row positive distances
__device__ unsigned char g_rsel[NNEGS * NROWS]; // resample idx, t-major [t][i]
__device__ int g_tile_ctr;                      // dynamic tile work counter
__device__ int g_rng_ctr;                       // completed rng CTAs

// ---------------------------------------------------------------------------
// Threefry-2x32-20, key (0, 42), exact JAX semantics; returns both words.
// ---------------------------------------------------------------------------
__device__ __forceinline__ void tf_block(unsigned lane, unsigned& o0, unsigned& o1) {
    const unsigned ks1 = 42u;
    const unsigned ks2 = 0x1BD11BDAu ^ 42u;
    unsigned x0 = lane;
    unsigned x1 = lane + HHALF + ks1;
#define TFR(r) { x0 += x1; x1 = (x1 << (r)) | (x1 >> (32 - (r))); x1 ^= x0; }
    TFR(13) TFR(15) TFR(26) TFR(6)   x0 += ks1; x1 += ks2 + 1u;
    TFR(17) TFR(29) TFR(16) TFR(24)  x0 += ks2; x1 += 0u  + 2u;
    TFR(13) TFR(15) TFR(26) TFR(6)   x0 += 0u;  x1 += ks1 + 3u;
    TFR(17) TFR(29) TFR(16) TFR(24)  x0 += ks1; x1 += ks2 + 4u;
    TFR(13) TFR(15) TFR(26) TFR(6)   x0 += ks2; x1 += 0u  + 5u;
#undef TFR
    o0 = x0; o1 = x1;
}

__device__ __forceinline__ float bits_to_u(unsigned bits) {
    return __uint_as_float((bits >> 9) | 0x3F800000u) - 1.0f;
}

__device__ __forceinline__ void cp16(unsigned sa, const void* g) {
    asm volatile("cp.async.cg.shared.global [%0], [%1], 16;\n" :: "r"(sa), "l"(g));
}

// ---------------------------------------------------------------------------
// Prep kernel: normalize + posdist (rng moved into the loss kernel).
//   blocks [0, 4096)    : row L2-normalize -> g_xb (bf16); block 0 also
//                         zeroes out and resets the work counters
//   blocks [4096, 4608) : per-class positive distances from RAW samples
// ---------------------------------------------------------------------------
__global__ __launch_bounds__(256) void prep_kernel(const float* __restrict__ x,
                                                   float* __restrict__ out,
                                                   int out_size) {
    __shared__ float sm[8 * DDIM + 16];
    int bid = blockIdx.x;
    int tid = threadIdx.x;

    if (bid < PREP_NORM) {
        if (bid == 0 && tid == 0) {
            for (int i = 0; i < out_size; i++) out[i] = 0.0f;
            g_tile_ctr = 0;
            g_rng_ctr = 0;
        }
        const float4* xin = (const float4*)(x + (size_t)bid * DDIM);
        float4 v = xin[tid];
        float ss = v.x * v.x + v.y * v.y + v.z * v.z + v.w * v.w;
        #pragma unroll
        for (int o = 16; o; o >>= 1) ss += __shfl_down_sync(0xffffffffu, ss, o);
        if ((tid & 31) == 0) sm[8 * DDIM + (tid >> 5)] = ss;
        __syncthreads();
        if (tid < 8) {
            float s2 = sm[8 * DDIM + tid];
            #pragma unroll
            for (int o = 4; o; o >>= 1) s2 += __shfl_down_sync(0xffu, s2, o);
            if (tid == 0) sm[8 * DDIM] = s2;
        }
        __syncthreads();
        float scale = 1.0f / fmaxf(sqrtf(sm[8 * DDIM]), 1e-8f);
        __nv_bfloat16 b[4];
        b[0] = __float2bfloat16(v.x * scale);
        b[1] = __float2bfloat16(v.y * scale);
        b[2] = __float2bfloat16(v.z * scale);
        b[3] = __float2bfloat16(v.w * scale);
        *(uint2*)(g_xb + (size_t)bid * DDIM + tid * 4) = *(uint2*)b;
    } else {
        // ---- positive distances for one class, self-normalizing ----
        int cls = bid - PREP_NORM;
        const float4* src = (const float4*)(x + (size_t)cls * 8 * DDIM);
        float4* dst = (float4*)sm;
        #pragma unroll
        for (int idx = tid; idx < 8 * DDIM / 4; idx += 256) dst[idx] = src[idx];
        __syncthreads();
        int w = tid >> 5, lane = tid & 31;
        {
            float s = 0.f;
            for (int e = lane; e < DDIM; e += 32) {
                float t = sm[w * DDIM + e];
                s += t * t;
            }
            #pragma unroll
            for (int o = 16; o; o >>= 1) s += __shfl_down_sync(0xffffffffu, s, o);
            if (lane == 0) sm[8 * DDIM + w] = 1.0f / fmaxf(sqrtf(s), 1e-8f);
        }
        __syncthreads();
        for (int q = w; q < 28; q += 8) {
            int a = 0, rem = q;
            while (rem >= 7 - a) { rem -= 7 - a; a++; }
            int b = a + 1 + rem;
            float s = 0.f;
            for (int e = lane; e < DDIM; e += 32) s += sm[a * DDIM + e] * sm[b * DDIM + e];
            #pragma unroll
            for (int o = 16; o; o >>= 1) s += __shfl_down_sync(0xffffffffu, s, o);
            if (lane == 0)
                g_dpos[(cls * 8 + a) * 8 + (b - a - 1)] =
                    1.0f - s * sm[8 * DDIM + a] * sm[8 * DDIM + b];
        }
    }
}

// ---------------------------------------------------------------------------
// Loss kernel: 296 persistent CTAs (2/SM, all resident in wave 1).
//   bids 0-147: compute the threefry rng table first (ALU pipes, overlapping
//               the co-resident tile CTA's tensor/L1-bound mainloop), signal
//               g_rng_ctr, then join tile processing.
//   all CTAs:   grab tiles from g_tile_ctr (dynamic balance). Per tile: bf16
//               mma.sync Gram (BK=32, 3-stage cp.async, R8-proven layout),
//               spin once for rng completion before the first epilogue, then
//               cooperative band staging + cheap unrolled epilogue.
// CTA = 128x128 tile, 512 threads, 16 warps, each warp 32x32 via m16n8k16.
// ---------------------------------------------------------------------------
__global__ __launch_bounds__(512, 2) void loss_kernel(float* __restrict__ out) {
    extern __shared__ char smc[];
    float* Dp = (float*)(smc + SM_DP);                     // 256 rows, stride 9
    int* ctl = (int*)(smc + SM_CTL);

    int tid = threadIdx.x;
    int w = tid >> 5, lane = tid & 31;
    int wr = w & 3, wc = w >> 2;            // warp tile: rows wr*32, cols wc*32
    int g = lane >> 2, t4 = lane & 3;

    // ---- phase 0: rng-role CTAs build the resample table ----
    if (blockIdx.x < NRNG) {
        #pragma unroll 2
        for (int k = 0; k < 100; k++) {
            unsigned gg = ((unsigned)k * (unsigned)NRNG + blockIdx.x) * 512u
                        + (unsigned)tid;
            if (gg < HHALF) {
                unsigned t = gg >> 11;
                unsigned i_low = gg & 2047u;
                int pi = 7 - (int)(i_low & 7u);
                if (pi == 0) {
                    g_rsel[t * NROWS + i_low] = 0xFFu;
                    g_rsel[t * NROWS + i_low + 2048] = 0xFFu;
                } else {
                    unsigned x0, x1;
                    tf_block(i_low * NNEGS + t, x0, x1);
                    float pf = (float)pi;
                    int r0 = min((int)(bits_to_u(x0) * pf), pi - 1);
                    int r1 = min((int)(bits_to_u(x1) * pf), pi - 1);
                    g_rsel[t * NROWS + i_low] = (unsigned char)r0;
                    g_rsel[t * NROWS + i_low + 2048] = (unsigned char)r1;
                }
            }
        }
        __syncthreads();
        __threadfence();
        if (tid == 0) atomicAdd(&g_rng_ctr, 1);
    }

    unsigned aBase = (unsigned)__cvta_generic_to_shared(smc + SM_ASM);
    unsigned bBase = (unsigned)__cvta_generic_to_shared(smc + SM_BSM);
    unsigned aAddr = aBase +
        (((unsigned)(wr * 32 + (lane & 15)) * 40 + ((lane & 16) ? 8u : 0u)) << 1);
    unsigned bAddr = bBase +
        (((unsigned)(wc * 32 + ((lane >> 4) & 1) * 8 + (lane & 7)) * 40 +
          ((lane & 8) ? 8u : 0u)) << 1);

    // cp.async per-thread slot: chunk tid of 512 16B-chunks per tile
    int lr = tid >> 2, lc = tid & 3;
    unsigned sa = (unsigned)(lr * 40 + lc * 8) * 2u;

    #define LOAD_STAGE(sidx, k0) do {                                          \
        unsigned ao = aBase + (unsigned)(sidx) * STG_BYTES;                    \
        unsigned bo = bBase + (unsigned)(sidx) * STG_BYTES;                    \
        cp16(ao + sa, &g_xb[(size_t)(rowA + lr) * DDIM + (k0) + lc * 8]);      \
        cp16(bo + sa, &g_xb[(size_t)(rowB + lr) * DDIM + (k0) + lc * 8]);      \
        asm volatile("cp.async.commit_group;\n" ::: "memory");                 \
    } while (0)

    bool rng_ok = false;
    for (;;) {
        if (tid == 0) *ctl = atomicAdd(&g_tile_ctr, 1);
        __syncthreads();
        int kblk = *ctl;
        if (kblk >= NTILE) break;

        // decode kblk -> (by, bx), bx >= by; off-diagonal pairs first
        int by, bx;
        if (kblk < (TTILES * (TTILES - 1)) / 2) {
            int e = (int)((63.0f - sqrtf(3969.0f - 8.0f * (float)kblk)) * 0.5f);
            while ((e + 1) * (TTILES - 1) - ((e + 1) * e) / 2 <= kblk) e++;
            while (e * (TTILES - 1) - (e * (e - 1)) / 2 > kblk) e--;
            by = e;
            bx = by + 1 + (kblk - (by * (TTILES - 1) - (by * (by - 1)) / 2));
        } else {
            by = bx = kblk - (TTILES * (TTILES - 1)) / 2;
        }
        const bool offDiag = (bx != by);
        int rowA = by * 128, rowB = bx * 128;

        // stage positive-distance tables (stride 9 de-conflicts dp[ridx] LDS)
        if (tid < 256) {
            int r = tid & 127, which = tid >> 7;
            const float* src = &g_dpos[((which ? rowB : rowA) + r) * 8];
            float* dst = &Dp[(which * 128 + r) * 9];
            #pragma unroll
            for (int k = 0; k < 8; k++) dst[k] = src[k];
        }

        float acc[2][4][4];
        #pragma unroll
        for (int mt = 0; mt < 2; mt++)
            #pragma unroll
            for (int nt = 0; nt < 4; nt++)
                #pragma unroll
                for (int e = 0; e < 4; e++) acc[mt][nt][e] = 0.0f;

        const int NIT = DDIM / 32;   // 32 iterations
        LOAD_STAGE(0, 0);
        LOAD_STAGE(1, 32);

        for (int it = 0; it < NIT; it++) {
            if (it < NIT - 1) asm volatile("cp.async.wait_group 1;\n" ::: "memory");
            else              asm volatile("cp.async.wait_group 0;\n" ::: "memory");
            __syncthreads();
            // prefetch stage (it+2)%3 == stage (it-1)%3: its readers all
            // passed the barrier above (read happened in iter it-1).
            if (it + 2 < NIT) LOAD_STAGE((it + 2) % 3, (it + 2) * 32);

            unsigned bufOff = (unsigned)(it % 3) * STG_BYTES;
            #pragma unroll
            for (int s = 0; s < 2; s++) {         // two k16 steps per BK=32
                unsigned bf[4][2];
                #pragma unroll
                for (int ntp = 0; ntp < 2; ntp++) {
                    unsigned r0, r1, r2, r3;
                    asm volatile(
                        "ldmatrix.sync.aligned.m8n8.x4.shared.b16 {%0,%1,%2,%3}, [%4];"
                        : "=r"(r0), "=r"(r1), "=r"(r2), "=r"(r3)
                        : "r"(bAddr + bufOff + (unsigned)((ntp * 16 * 40 + s * 16) * 2)));
                    bf[2 * ntp][0] = r0; bf[2 * ntp][1] = r1;
                    bf[2 * ntp + 1][0] = r2; bf[2 * ntp + 1][1] = r3;
                }
                #pragma unroll
                for (int mt = 0; mt < 2; mt++) {
                    unsigned a0, a1, a2, a3;
                    asm volatile(
                        "ldmatrix.sync.aligned.m8n8.x4.shared.b16 {%0,%1,%2,%3}, [%4];"
                        : "=r"(a0), "=r"(a1), "=r"(a2), "=r"(a3)
                        : "r"(aAddr + bufOff + (unsigned)((mt * 16 * 40 + s * 16) * 2)));
                    #pragma unroll
                    for (int nt = 0; nt < 4; nt++) {
                        asm volatile(
                            "mma.sync.aligned.m16n8k16.row.col.f32.bf16.bf16.f32 "
                            "{%0,%1,%2,%3}, {%4,%5,%6,%7}, {%8,%9}, {%0,%1,%2,%3};"
                            : "+f"(acc[mt][nt][0]), "+f"(acc[mt][nt][1]),
                              "+f"(acc[mt][nt][2]), "+f"(acc[mt][nt][3])
                            : "r"(a0), "r"(a1), "r"(a2), "r"(a3),
                              "r"(bf[nt][0]), "r"(bf[nt][1]));
                    }
                }
            }
        }
        __syncthreads();    // all warps done with stage buffers before overlay

        // ---- first epilogue must wait for the rng table ----
        if (!rng_ok) {
            if (tid == 0)
                while (atomicAdd(&g_rng_ctr, 0) < NRNG) __nanosleep(200);
            __syncthreads();
            rng_ok = true;
        }

        // ---------------- cooperative band staging ----------------
        // fwd band (c_l,cj_l), chunk jo: rsel[(bef*8+jo)*4096 + rowA + c_l*8 ..+7]
        // rev band (c_l,cj_l), chunk io: rsel[(befr*8+io)*4096 + rowB + cj_l*8 ..+7]
        // invalid chunks (same class / t >= NNEGS / non-offDiag rev) -> 0xFF
        unsigned char* RF = (unsigned char*)(smc + SM_RF);
        unsigned char* RR = (unsigned char*)(smc + SM_RR);
        #pragma unroll
        for (int ss = 0; ss < 4; ss++) {
            int cid = tid + ss * 512;                 // 0..2047
            int c_l = cid >> 7, cj_l = (cid >> 3) & 15, jo = cid & 7;
            int c = by * 16 + c_l, cj = bx * 16 + cj_l;
            int dd = abs(c - cj);
            int bef = max(0, c - dd) + max(0, (NCLS - 1) - c - dd)
                    + ((cj > c && c >= dd) ? 1 : 0);
            int t = bef * 8 + jo;
            uint2 v = make_uint2(0xFFFFFFFFu, 0xFFFFFFFFu);
            if (c != cj && t < NNEGS)
                v = *(const uint2*)&g_rsel[(unsigned)t * NROWS + (unsigned)(rowA + c_l * 8)];
            *(uint2*)&RF[cid * 8] = v;

            int befr = max(0, cj - dd) + max(0, (NCLS - 1) - cj - dd)
                     + ((c > cj && cj >= dd) ? 1 : 0);
            int tr = befr * 8 + jo;                   // jo plays the role of io
            uint2 vr = make_uint2(0xFFFFFFFFu, 0xFFFFFFFFu);
            if (offDiag && tr < NNEGS)
                vr = *(const uint2*)&g_rsel[(unsigned)tr * NROWS + (unsigned)(rowB + cj_l * 8)];
            *(uint2*)&RR[cid * 8] = vr;
        }
        __syncthreads();

        // ---------------- fully-unrolled epilogue ----------------
        const float MC = MARGINF - 1.0f;
        float lsum = 0.0f;
        #pragma unroll
        for (int mr = 0; mr < 4; mr++) {
            int mt = mr >> 1, rh = mr & 1;
            int c_l = wr * 4 + mt * 2 + rh;
            int il = c_l * 8 + g;
            const float* dpi = &Dp[il * 9];
            #pragma unroll
            for (int nt = 0; nt < 4; nt++) {
                int cj_l = wc * 4 + nt;
                const unsigned char* bF = &RF[(c_l * 16 + cj_l) * 64];
                const unsigned char* bR = &RR[(c_l * 16 + cj_l) * 64];
                #pragma unroll
                for (int ch = 0; ch < 2; ch++) {
                    int jq = 2 * t4 + ch;
                    float s = acc[mt][nt][rh * 2 + ch];
                    int rf = bF[jq * 8 + g];
                    if (rf != 255)
                        lsum += fmaxf(dpi[rf] + s + MC, 0.0f);
                    if (offDiag) {
                        int rr = bR[g * 8 + jq];
                        if (rr != 255) {
                            int jl = wc * 32 + nt * 8 + jq;
                            lsum += fmaxf(Dp[(128 + jl) * 9 + rr] + s + MC, 0.0f);
                        }
                    }
                }
            }
        }

        // block reduction -> one atomicAdd per CTA per tile (Dp as scratch)
        #pragma unroll
        for (int o = 16; o; o >>= 1) lsum += __shfl_down_sync(0xffffffffu, lsum, o);
        __syncthreads();                       // everyone done reading Dp
        if ((tid & 31) == 0) Dp[tid >> 5] = lsum;
        __syncthreads();
        if (tid < 16) {
            float s2 = Dp[tid];
            #pragma unroll
            for (int o = 8; o; o >>= 1) s2 += __shfl_down_sync(0xffffu, s2, o);
            if (tid == 0) atomicAdd(out, s2);
        }
        __syncthreads();    // protect Dp/ctl before next tile
    }
}

// ---------------------------------------------------------------------------
extern "C" void kernel_launch(void* const* d_in, const int* in_sizes, int n_in,
                              void* d_out, int out_size) {
    const float* samples = (const float*)d_in[0];
    float* out = (float*)d_out;

    cudaFuncSetAttribute(loss_kernel,
                         cudaFuncAttributeMaxDynamicSharedMemorySize, SM_TOTAL);
    prep_kernel<<<PREP_GRID, 256>>>(samples, out, out_size);
    loss_kernel<<<NPERS, 512, SM_TOTAL>>>(out);
}

// round 13
// speedup vs baseline: 1.2002x; 1.2002x over previous
#include <cuda_runtime.h>
#include <cuda_bf16.h>
#include <cstdint>

// Problem constants (fixed by the dataset instance)
#define NROWS  4096
#define DDIM   1024
#define NCLS   512
#define NNEGS  3679
#define HHALF  7534592u        // n/2 for threefry lane pairing, n = 4096*3679
#define MARGINF 0.15f
#define TTILES 32              // 4096 / 128

// loss kernel dynamic smem layout (bytes)  [R8-proven]
#define STG_BYTES 10240                 // one stage, one matrix: 128*40*2
#define SM_ASM   0                      // 3 stages A: [0, 30720)
#define SM_BSM   30720                  // 3 stages B: [30720, 61440)
#define SM_DP    61440                  // Dp: 256 rows * 9 floats = 9216
#define SM_TOTAL 70656
// epilogue staging overlays (stage buffers are dead after the mainloop)
#define SM_RF    0                      // fwd bands, 16 KB
#define SM_RR    30720                  // rev bands, 16 KB

// prep kernel grid split: rng slabs FIRST (longest pole starts immediately)
#define PREP_RNG   NNEGS                          // 3679 blocks, one per t
#define PREP_NORM  (PREP_RNG + NROWS)             // 7775
#define PREP_GRID  (PREP_NORM + NCLS)             // 8287

// Scratch (static __device__ arrays: allocation-free)
__device__ __nv_bfloat16 g_xb[NROWS * DDIM];    // normalized samples, bf16
__device__ float g_dpos[NROWS * 8];             // per-row positive distances
__device__ unsigned char g_rsel[NNEGS * NROWS]; // resample idx, t-major [t][i]

// ---------------------------------------------------------------------------
// Threefry-2x32-20, key (0, 42), exact JAX semantics; returns both words.
// ---------------------------------------------------------------------------
__device__ __forceinline__ void tf_block(unsigned lane, unsigned& o0, unsigned& o1) {
    const unsigned ks1 = 42u;
    const unsigned ks2 = 0x1BD11BDAu ^ 42u;
    unsigned x0 = lane;
    unsigned x1 = lane + HHALF + ks1;
#define TFR(r) { x0 += x1; x1 = (x1 << (r)) | (x1 >> (32 - (r))); x1 ^= x0; }
    TFR(13) TFR(15) TFR(26) TFR(6)   x0 += ks1; x1 += ks2 + 1u;
    TFR(17) TFR(29) TFR(16) TFR(24)  x0 += ks2; x1 += 0u  + 2u;
    TFR(13) TFR(15) TFR(26) TFR(6)   x0 += 0u;  x1 += ks1 + 3u;
    TFR(17) TFR(29) TFR(16) TFR(24)  x0 += ks1; x1 += ks2 + 4u;
    TFR(13) TFR(15) TFR(26) TFR(6)   x0 += ks2; x1 += 0u  + 5u;
#undef TFR
    o0 = x0; o1 = x1;
}

__device__ __forceinline__ float bits_to_u(unsigned bits) {
    return __uint_as_float((bits >> 9) | 0x3F800000u) - 1.0f;
}

__device__ __forceinline__ void cp16(unsigned sa, const void* g) {
    asm volatile("cp.async.cg.shared.global [%0], [%1], 16;\n" :: "r"(sa), "l"(g));
}

// ---------------------------------------------------------------------------
// Prep kernel: three independent sections run concurrently in one launch.
//   blocks [0, 3679)      : threefry rng slabs (block = one t, ILP-6/thread)
//   blocks [3679, 7775)   : row L2-normalize -> g_xb; block start zeroes out
//   blocks [7775, 8287)   : per-class positive distances from RAW samples
// ---------------------------------------------------------------------------
__global__ __launch_bounds__(256) void prep_kernel(const float* __restrict__ x,
                                                   float* __restrict__ out,
                                                   int out_size) {
    __shared__ float sm[8 * DDIM + 16];
    int bid = blockIdx.x;
    int tid = threadIdx.x;

    if (bid < PREP_RNG) {
        // ---- rng slab: t = bid; thread owns rows i_low = tid*8+k, k=0..7.
        // pi = 7-k: k=6 -> ridx always 0 (no rng), k=7 -> invalid (0xFF).
        // Six INDEPENDENT threefry chains per thread (k=0..5) for ILP.
        unsigned t = (unsigned)bid;
        unsigned ibase = (unsigned)tid * 8u;
        unsigned lowA[8], lowB[8];              // bytes for i_low / i_low+2048
        #pragma unroll
        for (int k = 0; k < 6; k++) {
            unsigned x0, x1;
            tf_block((ibase + k) * NNEGS + t, x0, x1);
            float pf = (float)(7 - k);
            int pm1 = 6 - k;
            lowA[k] = (unsigned)min((int)(bits_to_u(x0) * pf), pm1);
            lowB[k] = (unsigned)min((int)(bits_to_u(x1) * pf), pm1);
        }
        lowA[6] = 0u;    lowB[6] = 0u;          // pi = 1 -> ridx 0
        lowA[7] = 0xFFu; lowB[7] = 0xFFu;       // pi = 0 -> invalid
        uint2 va, vb;
        va.x = lowA[0] | (lowA[1] << 8) | (lowA[2] << 16) | (lowA[3] << 24);
        va.y = lowA[4] | (lowA[5] << 8) | (lowA[6] << 16) | (lowA[7] << 24);
        vb.x = lowB[0] | (lowB[1] << 8) | (lowB[2] << 16) | (lowB[3] << 24);
        vb.y = lowB[4] | (lowB[5] << 8) | (lowB[6] << 16) | (lowB[7] << 24);
        *(uint2*)&g_rsel[t * NROWS + ibase] = va;
        *(uint2*)&g_rsel[t * NROWS + 2048u + ibase] = vb;
    } else if (bid < PREP_NORM) {
        // ---- normalize one row ----
        int row = bid - PREP_RNG;
        if (row == 0 && tid == 0)
            for (int i = 0; i < out_size; i++) out[i] = 0.0f;
        const float4* xin = (const float4*)(x + (size_t)row * DDIM);
        float4 v = xin[tid];
        float ss = v.x * v.x + v.y * v.y + v.z * v.z + v.w * v.w;
        #pragma unroll
        for (int o = 16; o; o >>= 1) ss += __shfl_down_sync(0xffffffffu, ss, o);
        if ((tid & 31) == 0) sm[8 * DDIM + (tid >> 5)] = ss;
        __syncthreads();
        if (tid < 8) {
            float s2 = sm[8 * DDIM + tid];
            #pragma unroll
            for (int o = 4; o; o >>= 1) s2 += __shfl_down_sync(0xffu, s2, o);
            if (tid == 0) sm[8 * DDIM] = s2;
        }
        __syncthreads();
        float scale = 1.0f / fmaxf(sqrtf(sm[8 * DDIM]), 1e-8f);
        __nv_bfloat16 b[4];
        b[0] = __float2bfloat16(v.x * scale);
        b[1] = __float2bfloat16(v.y * scale);
        b[2] = __float2bfloat16(v.z * scale);
        b[3] = __float2bfloat16(v.w * scale);
        *(uint2*)(g_xb + (size_t)row * DDIM + tid * 4) = *(uint2*)b;
    } else {
        // ---- positive distances for one class, self-normalizing ----
        int cls = bid - PREP_NORM;
        const float4* src = (const float4*)(x + (size_t)cls * 8 * DDIM);
        float4* dst = (float4*)sm;
        #pragma unroll
        for (int idx = tid; idx < 8 * DDIM / 4; idx += 256) dst[idx] = src[idx];
        __syncthreads();
        int w = tid >> 5, lane = tid & 31;
        {
            float s = 0.f;
            for (int e = lane; e < DDIM; e += 32) {
                float t = sm[w * DDIM + e];
                s += t * t;
            }
            #pragma unroll
            for (int o = 16; o; o >>= 1) s += __shfl_down_sync(0xffffffffu, s, o);
            if (lane == 0) sm[8 * DDIM + w] = 1.0f / fmaxf(sqrtf(s), 1e-8f);
        }
        __syncthreads();
        for (int q = w; q < 28; q += 8) {
            int a = 0, rem = q;
            while (rem >= 7 - a) { rem -= 7 - a; a++; }
            int b = a + 1 + rem;
            float s = 0.f;
            for (int e = lane; e < DDIM; e += 32) s += sm[a * DDIM + e] * sm[b * DDIM + e];
            #pragma unroll
            for (int o = 16; o; o >>= 1) s += __shfl_down_sync(0xffffffffu, s, o);
            if (lane == 0)
                g_dpos[(cls * 8 + a) * 8 + (b - a - 1)] =
                    1.0f - s * sm[8 * DDIM + a] * sm[8 * DDIM + b];
        }
    }
}

// ---------------------------------------------------------------------------
// Loss kernel [exact R8, 84.8us proven]: bf16 mma.sync Gram (triangular grid,
// 528 CTAs, off-diagonal first), 3-stage cp.async pipeline with ONE
// __syncthreads per iteration, then cooperative band staging + epilogue.
// CTA = 128x128 tile, 512 threads, 16 warps, each warp 32x32 via m16n8k16.
// 64 regs/thread -> 2 CTAs/SM -> 32 warps/SM.
// ---------------------------------------------------------------------------
__global__ __launch_bounds__(512, 2) void loss_kernel(float* __restrict__ out) {
    // decode blockIdx.x -> (by, bx), bx >= by; off-diagonal pairs first
    int kblk = blockIdx.x;
    int by, bx;
    if (kblk < (TTILES * (TTILES - 1)) / 2) {
        int e = (int)((63.0f - sqrtf(3969.0f - 8.0f * (float)kblk)) * 0.5f);
        while ((e + 1) * (TTILES - 1) - ((e + 1) * e) / 2 <= kblk) e++;
        while (e * (TTILES - 1) - (e * (e - 1)) / 2 > kblk) e--;
        by = e;
        bx = by + 1 + (kblk - (by * (TTILES - 1) - (by * (by - 1)) / 2));
    } else {
        by = bx = kblk - (TTILES * (TTILES - 1)) / 2;
    }
    const bool offDiag = (bx != by);
    int rowA = by * 128, rowB = bx * 128;

    extern __shared__ char smc[];
    float* Dp = (float*)(smc + SM_DP);                     // 256 rows, stride 9

    int tid = threadIdx.x;
    int w = tid >> 5, lane = tid & 31;
    int wr = w & 3, wc = w >> 2;            // warp tile: rows wr*32, cols wc*32
    int g = lane >> 2, t4 = lane & 3;

    // stage positive-distance tables (stride 9 to de-conflict dp[ridx] LDS)
    if (tid < 256) {
        int r = tid & 127, which = tid >> 7;
        const float* src = &g_dpos[((which ? rowB : rowA) + r) * 8];
        float* dst = &Dp[(which * 128 + r) * 9];
        #pragma unroll
        for (int k = 0; k < 8; k++) dst[k] = src[k];
    }

    float acc[2][4][4];
    #pragma unroll
    for (int mt = 0; mt < 2; mt++)
        #pragma unroll
        for (int nt = 0; nt < 4; nt++)
            #pragma unroll
            for (int e = 0; e < 4; e++) acc[mt][nt][e] = 0.0f;

    unsigned aBase = (unsigned)__cvta_generic_to_shared(smc + SM_ASM);
    unsigned bBase = (unsigned)__cvta_generic_to_shared(smc + SM_BSM);
    unsigned aAddr = aBase +
        (((unsigned)(wr * 32 + (lane & 15)) * 40 + ((lane & 16) ? 8u : 0u)) << 1);
    unsigned bAddr = bBase +
        (((unsigned)(wc * 32 + ((lane >> 4) & 1) * 8 + (lane & 7)) * 40 +
          ((lane & 8) ? 8u : 0u)) << 1);

    // per-thread load slot: chunk tid of 512 16B-chunks per tile
    int lr = tid >> 2, lc = tid & 3;
    unsigned sa = (unsigned)(lr * 40 + lc * 8) * 2u;

    const int NIT = DDIM / 32;   // 32 iterations

    #define LOAD_STAGE(sidx, k0) do {                                          \
        unsigned ao = aBase + (unsigned)(sidx) * STG_BYTES;                    \
        unsigned bo = bBase + (unsigned)(sidx) * STG_BYTES;                    \
        cp16(ao + sa, &g_xb[(size_t)(rowA + lr) * DDIM + (k0) + lc * 8]);      \
        cp16(bo + sa, &g_xb[(size_t)(rowB + lr) * DDIM + (k0) + lc * 8]);      \
        asm volatile("cp.async.commit_group;\n" ::: "memory");                 \
    } while (0)

    LOAD_STAGE(0, 0);
    LOAD_STAGE(1, 32);

    for (int it = 0; it < NIT; it++) {
        if (it < NIT - 1) asm volatile("cp.async.wait_group 1;\n" ::: "memory");
        else              asm volatile("cp.async.wait_group 0;\n" ::: "memory");
        __syncthreads();
        // prefetch stage (it+2)%3 == stage (it-1)%3: its readers all
        // passed the barrier above (read happened in iter it-1).
        if (it + 2 < NIT) LOAD_STAGE((it + 2) % 3, (it + 2) * 32);

        unsigned bufOff = (unsigned)(it % 3) * STG_BYTES;
        #pragma unroll
        for (int s = 0; s < 2; s++) {         // two k16 steps per BK=32
            unsigned bf[4][2];
            #pragma unroll
            for (int ntp = 0; ntp < 2; ntp++) {
                unsigned r0, r1, r2, r3;
                asm volatile(
                    "ldmatrix.sync.aligned.m8n8.x4.shared.b16 {%0,%1,%2,%3}, [%4];"
                    : "=r"(r0), "=r"(r1), "=r"(r2), "=r"(r3)
                    : "r"(bAddr + bufOff + (unsigned)((ntp * 16 * 40 + s * 16) * 2)));
                bf[2 * ntp][0] = r0; bf[2 * ntp][1] = r1;
                bf[2 * ntp + 1][0] = r2; bf[2 * ntp + 1][1] = r3;
            }
            #pragma unroll
            for (int mt = 0; mt < 2; mt++) {
                unsigned a0, a1, a2, a3;
                asm volatile(
                    "ldmatrix.sync.aligned.m8n8.x4.shared.b16 {%0,%1,%2,%3}, [%4];"
                    : "=r"(a0), "=r"(a1), "=r"(a2), "=r"(a3)
                    : "r"(aAddr + bufOff + (unsigned)((mt * 16 * 40 + s * 16) * 2)));
                #pragma unroll
                for (int nt = 0; nt < 4; nt++) {
                    asm volatile(
                        "mma.sync.aligned.m16n8k16.row.col.f32.bf16.bf16.f32 "
                        "{%0,%1,%2,%3}, {%4,%5,%6,%7}, {%8,%9}, {%0,%1,%2,%3};"
                        : "+f"(acc[mt][nt][0]), "+f"(acc[mt][nt][1]),
                          "+f"(acc[mt][nt][2]), "+f"(acc[mt][nt][3])
                        : "r"(a0), "r"(a1), "r"(a2), "r"(a3),
                          "r"(bf[nt][0]), "r"(bf[nt][1]));
                }
            }
        }
    }
    __syncthreads();    // all warps done with stage buffers before overlay

    // ---------------- cooperative band staging ----------------
    // fwd band (c_l,cj_l), chunk jo: rsel[(bef*8+jo)*4096 + rowA + c_l*8 ..+7]
    // rev band (c_l,cj_l), chunk io: rsel[(befr*8+io)*4096 + rowB + cj_l*8 ..+7]
    // invalid chunks (same class / t >= NNEGS / non-offDiag rev) -> 0xFF
    unsigned char* RF = (unsigned char*)(smc + SM_RF);
    unsigned char* RR = (unsigned char*)(smc + SM_RR);
    #pragma unroll
    for (int ss = 0; ss < 4; ss++) {
        int cid = tid + ss * 512;                 // 0..2047
        int c_l = cid >> 7, cj_l = (cid >> 3) & 15, jo = cid & 7;
        int c = by * 16 + c_l, cj = bx * 16 + cj_l;
        int dd = abs(c - cj);
        int bef = max(0, c - dd) + max(0, (NCLS - 1) - c - dd)
                + ((cj > c && c >= dd) ? 1 : 0);
        int t = bef * 8 + jo;
        uint2 v = make_uint2(0xFFFFFFFFu, 0xFFFFFFFFu);
        if (c != cj && t < NNEGS)
            v = *(const uint2*)&g_rsel[(unsigned)t * NROWS + (unsigned)(rowA + c_l * 8)];
        *(uint2*)&RF[cid * 8] = v;

        int befr = max(0, cj - dd) + max(0, (NCLS - 1) - cj - dd)
                 + ((c > cj && cj >= dd) ? 1 : 0);
        int tr = befr * 8 + jo;                   // jo plays the role of io
        uint2 vr = make_uint2(0xFFFFFFFFu, 0xFFFFFFFFu);
        if (offDiag && tr < NNEGS)
            vr = *(const uint2*)&g_rsel[(unsigned)tr * NROWS + (unsigned)(rowB + cj_l * 8)];
        *(uint2*)&RR[cid * 8] = vr;
    }
    __syncthreads();

    // ---------------- fully-unrolled epilogue ----------------
    const float MC = MARGINF - 1.0f;
    float lsum = 0.0f;
    #pragma unroll
    for (int mr = 0; mr < 4; mr++) {
        int mt = mr >> 1, rh = mr & 1;
        int c_l = wr * 4 + mt * 2 + rh;
        int il = c_l * 8 + g;
        const float* dpi = &Dp[il * 9];
        #pragma unroll
        for (int nt = 0; nt < 4; nt++) {
            int cj_l = wc * 4 + nt;
            const unsigned char* bF = &RF[(c_l * 16 + cj_l) * 64];
            const unsigned char* bR = &RR[(c_l * 16 + cj_l) * 64];
            #pragma unroll
            for (int ch = 0; ch < 2; ch++) {
                int jq = 2 * t4 + ch;
                float s = acc[mt][nt][rh * 2 + ch];
                int rf = bF[jq * 8 + g];
                if (rf != 255)
                    lsum += fmaxf(dpi[rf] + s + MC, 0.0f);
                if (offDiag) {
                    int rr = bR[g * 8 + jq];
                    if (rr != 255) {
                        int jl = wc * 32 + nt * 8 + jq;
                        lsum += fmaxf(Dp[(128 + jl) * 9 + rr] + s + MC, 0.0f);
                    }
                }
            }
        }
    }

    // block reduction -> one atomicAdd per CTA (reuse Dp as scratch)
    #pragma unroll
    for (int o = 16; o; o >>= 1) lsum += __shfl_down_sync(0xffffffffu, lsum, o);
    __syncthreads();                       // everyone done reading Dp
    if ((tid & 31) == 0) Dp[tid >> 5] = lsum;
    __syncthreads();
    if (tid < 16) {
        float s2 = Dp[tid];
        #pragma unroll
        for (int o = 8; o; o >>= 1) s2 += __shfl_down_sync(0xffffu, s2, o);
        if (tid == 0) atomicAdd(out, s2);
    }
}

// ---------------------------------------------------------------------------
extern "C" void kernel_launch(void* const* d_in, const int* in_sizes, int n_in,
                              void* d_out, int out_size) {
    const float* samples = (const float*)d_in[0];
    float* out = (float*)d_out;

    cudaFuncSetAttribute(loss_kernel,
                         cudaFuncAttributeMaxDynamicSharedMemorySize, SM_TOTAL);
    prep_kernel<<<PREP_GRID, 256>>>(samples, out, out_size);
    loss_kernel<<<(TTILES * (TTILES + 1)) / 2, 512, SM_TOTAL>>>(out);
}